// round 9
// baseline (speedup 1.0000x reference)
#include <cuda_runtime.h>

// BackProjection: B=2, A=180, HR=512, H=W=512, pad=51, Hp=Wp=614
#define A_N   180
#define HR_N  512
#define HOUT  512
#define HP    614
#define PADR  64            // zero-pad rows each side (covers y0 in [-56, 667])
#define HPP   (HP + 2*PADR) // 742 rows per angle

// Zero-padded per-angle column profile, both batches + next row fused:
// row y (logical, y in [-PADR, HP+PADR)) holds (b0[y], b1[y], b0[y+1], b1[y+1])
// where b*[y] == 0 outside [0, HP-1]. One LDG.128 gives a full bilinear-y pair.
__device__ float4 g_col4p[A_N * HPP];

__device__ __forceinline__ float2 col_at(const float* __restrict__ sino, int a, int y) {
    float src = ((float)y + 0.5f) * ((float)HR_N / (float)HP) - 0.5f;
    src = fminf(fmaxf(src, 0.0f), (float)(HR_N - 1));
    int i0 = (int)src;                       // src >= 0
    int i1 = min(i0 + 1, HR_N - 1);
    float w = src - (float)i0;
    const float* s0 = sino + a * HR_N;                 // b = 0
    const float* s1 = sino + A_N * HR_N + a * HR_N;    // b = 1
    // match reference rounding: p0*(1-w) + p1*w
    float v0 = s0[i0] * (1.0f - w) + s0[i1] * w;
    float v1 = s1[i0] * (1.0f - w) + s1[i1] * w;
    return make_float2(v0, v1);
}

__global__ void col_kernel(const float* __restrict__ sino) {
    int idx = blockIdx.x * blockDim.x + threadIdx.x;
    if (idx >= A_N * HPP) return;
    int a  = idx / HPP;
    int y  = idx - a * HPP - PADR;          // logical row
    float2 c0 = (y     >= 0 && y     < HP) ? col_at(sino, a, y)     : make_float2(0.f, 0.f);
    float2 c1 = (y + 1 >= 0 && y + 1 < HP) ? col_at(sino, a, y + 1) : make_float2(0.f, 0.f);
    g_col4p[idx] = make_float4(c0.x, c0.y, c1.x, c1.y);
}

__global__ __launch_bounds__(256, 7) void bp_kernel(const float* __restrict__ angles,
                                                    float* __restrict__ out) {
    __shared__ float2 sh_cs[A_N];   // (cos, sin) of th = -deg2rad(angle)
    int t = threadIdx.x;
    if (t < A_N) {
        float th = -angles[t] * 0.017453292519943295f;
        sh_cs[t] = make_float2(cosf(th), sinf(th));
    }
    __syncthreads();

    // 2-D warp footprint: each warp covers an 8x4 pixel tile so its per-angle
    // gather addresses span only ~7|s|+3|c| table rows (vs 31|s| for 32x1),
    // cutting L1 wavefronts per load ~2x. CTA tile 32x8 = 4x2 grid of warps.
    int warp = t >> 5;
    int lane = t & 31;
    int x = blockIdx.x * 32 + (warp & 3) * 8 + (lane & 7);
    int y = blockIdx.y * 8  + (warp >> 2) * 4 + (lane >> 3);

    // padded coords (x+51), center 306.5:  X = (x+51) - 306.5 = x - 255.5
    float Xp = (float)x - 255.5f;
    float Yp = (float)y - 255.5f;

    float a0x = 0.0f, a0y = 0.0f, a1x = 0.0f, a1y = 0.0f;

    // Interior: r^2 < 93500 (r < 305.8) => ix, iy in (0.5, 612.5) for all angles:
    // all 4 corners valid, wxe == 1, y0 in [0,612]. Warp-uniform branch so a
    // straddling warp executes exactly ONE of the two loops.
    bool interior = fmaf(Xp, Xp, Yp * Yp) < 93500.0f;

    if (__all_sync(0xffffffffu, interior)) {
        const float4* __restrict__ colA = g_col4p + PADR;
        #pragma unroll 4
        for (int a = 0; a < A_N; a += 2, colA += 2 * HPP) {
            {
                float2 cs = sh_cs[a];
                float iy = fmaf(cs.y, Xp, fmaf(cs.x, Yp, 306.5f));
                int   y0 = (int)iy;                 // iy > 0 -> trunc == floor
                float wy = iy - (float)y0;
                float4 cc = colA[y0];
                float w0 = 1.0f - wy;
                a0x = fmaf(w0, cc.x, a0x);
                a0y = fmaf(w0, cc.y, a0y);
                a0x = fmaf(wy, cc.z, a0x);
                a0y = fmaf(wy, cc.w, a0y);
            }
            {
                float2 cs = sh_cs[a + 1];
                float iy = fmaf(cs.y, Xp, fmaf(cs.x, Yp, 306.5f));
                int   y0 = (int)iy;
                float wy = iy - (float)y0;
                float4 cc = colA[HPP + y0];
                float w0 = 1.0f - wy;
                a1x = fmaf(w0, cc.x, a1x);
                a1y = fmaf(w0, cc.y, a1y);
                a1x = fmaf(wy, cc.z, a1x);
                a1y = fmaf(wy, cc.w, a1y);
            }
        }
    } else {
        // General path. Zero-padded table removes all y masking/clamping;
        // x masking collapses to wxe = clamp(min(ix+1, 614-ix), 0, 1):
        //   ix in [-1,0):  vx0=0, vx1=1 -> wxe = wx   = ix+1
        //   ix in [0,613): vx0=vx1=1    -> wxe = 1
        //   ix in [613,614): vx0=1,vx1=0-> wxe = 1-wx = 614-ix
        //   else 0.
        const float4* __restrict__ colA = g_col4p + PADR;
        #pragma unroll 2
        for (int a = 0; a < A_N; ++a, colA += HPP) {
            float2 cs = sh_cs[a];
            float c = cs.x, s = cs.y;
            float ix = fmaf(c, Xp, fmaf(-s, Yp, 306.5f));
            float iy = fmaf(s, Xp, fmaf(c, Yp, 306.5f));
            float wxe = fmaxf(fminf(fminf(ix + 1.0f, 614.0f - ix), 1.0f), 0.0f);
            float y0f = floorf(iy);
            int   y0  = (int)y0f;               // in [-56, 667] -> padded range
            float wy  = iy - y0f;
            float4 cc = colA[y0];
            float w0 = (1.0f - wy) * wxe;
            float w1 = wy * wxe;
            a0x = fmaf(w0, cc.x, a0x);
            a0y = fmaf(w0, cc.y, a0y);
            a0x = fmaf(w1, cc.z, a0x);
            a0y = fmaf(w1, cc.w, a0y);
        }
    }

    const float scale = (float)(1.0 / (180.0 + 1e-6));
    int o = y * HOUT + x;
    out[o]               = (a0x + a1x) * scale;
    out[o + HOUT * HOUT] = (a0y + a1y) * scale;   // batch 1 (out shape (2,1,512,512))
}

extern "C" void kernel_launch(void* const* d_in, const int* in_sizes, int n_in,
                              void* d_out, int out_size) {
    const float* sino   = (const float*)d_in[0];
    const float* angles = (const float*)d_in[1];
    float* out = (float*)d_out;

    col_kernel<<<(A_N * HPP + 255) / 256, 256>>>(sino);

    dim3 blk(256, 1);
    dim3 grd(HOUT / 32, HOUT / 8);   // 16 x 64 = 1024 CTAs, single resident wave
    bp_kernel<<<grd, blk>>>(angles, out);
}

// round 10
// speedup vs baseline: 1.0787x; 1.0787x over previous
#include <cuda_runtime.h>
#include <cuda_fp16.h>

// BackProjection: B=2, A=180, HR=512, H=W=512, pad=51, Hp=Wp=614
#define A_N   180
#define HR_N  512
#define HOUT  512
#define HP    614
#define PADR  64            // zero-pad rows each side (covers y0 in [-56, 667])
#define HPP   (HP + 2*PADR) // 742 rows per angle

// Zero-padded per-angle column profile in fp16, both batches + next row fused:
// entry.x = half2(b0[y], b1[y]); entry.y = half2(b0[y+1], b1[y+1]),
// with b*[y] == 0 outside [0, HP-1]. One LDG.64 gives a full bilinear-y pair
// for both batches (2 L1 wavefronts/warp-load vs 4 for float4).
__device__ uint2 g_colh[A_N * HPP];

__device__ __forceinline__ float2 col_at(const float* __restrict__ sino, int a, int y) {
    float src = ((float)y + 0.5f) * ((float)HR_N / (float)HP) - 0.5f;
    src = fminf(fmaxf(src, 0.0f), (float)(HR_N - 1));
    int i0 = (int)src;                       // src >= 0
    int i1 = min(i0 + 1, HR_N - 1);
    float w = src - (float)i0;
    const float* s0 = sino + a * HR_N;                 // b = 0
    const float* s1 = sino + A_N * HR_N + a * HR_N;    // b = 1
    // match reference rounding: p0*(1-w) + p1*w
    float v0 = s0[i0] * (1.0f - w) + s0[i1] * w;
    float v1 = s1[i0] * (1.0f - w) + s1[i1] * w;
    return make_float2(v0, v1);
}

__global__ void col_kernel(const float* __restrict__ sino) {
    int idx = blockIdx.x * blockDim.x + threadIdx.x;
    if (idx >= A_N * HPP) return;
    int a  = idx / HPP;
    int y  = idx - a * HPP - PADR;          // logical row
    float2 c0 = (y     >= 0 && y     < HP) ? col_at(sino, a, y)     : make_float2(0.f, 0.f);
    float2 c1 = (y + 1 >= 0 && y + 1 < HP) ? col_at(sino, a, y + 1) : make_float2(0.f, 0.f);
    __half2 h0 = __floats2half2_rn(c0.x, c0.y);
    __half2 h1 = __floats2half2_rn(c1.x, c1.y);
    uint2 e;
    e.x = *reinterpret_cast<unsigned*>(&h0);
    e.y = *reinterpret_cast<unsigned*>(&h1);
    g_colh[idx] = e;
}

__global__ __launch_bounds__(256, 7) void bp_kernel(const float* __restrict__ angles,
                                                    float* __restrict__ out) {
    __shared__ float2 sh_cs[A_N];   // (cos, sin) of th = -deg2rad(angle)
    int t = threadIdx.y * 32 + threadIdx.x;
    if (t < A_N) {
        float th = -angles[t] * 0.017453292519943295f;
        sh_cs[t] = make_float2(cosf(th), sinf(th));
    }
    __syncthreads();

    // 32x1 warp layout (proven best): coalesced loads/stores.
    int x = blockIdx.x * 32 + threadIdx.x;
    int y = blockIdx.y * 8 + threadIdx.y;
    // padded coords (x+51), center 306.5:  X = (x+51) - 306.5 = x - 255.5
    float Xp = (float)x - 255.5f;
    float Yp = (float)y - 255.5f;

    float a0x = 0.0f, a0y = 0.0f, a1x = 0.0f, a1y = 0.0f;

    // Interior: r^2 < 93500 (r < 305.8) => ix, iy in (0.5, 612.5) for all angles:
    // all 4 corners valid, wxe == 1, y0 in [0,612]. Warp-uniform branch so a
    // straddling warp executes exactly ONE of the two loops.
    bool interior = fmaf(Xp, Xp, Yp * Yp) < 93500.0f;

    if (__all_sync(0xffffffffu, interior)) {
        const uint2* __restrict__ colA = g_colh + PADR;
        #pragma unroll 4
        for (int a = 0; a < A_N; a += 2, colA += 2 * HPP) {
            {
                float2 cs = sh_cs[a];
                float iy = fmaf(cs.y, Xp, fmaf(cs.x, Yp, 306.5f));
                int   y0 = (int)iy;                 // iy > 0 -> trunc == floor
                float wy = iy - (float)y0;
                uint2 cc = colA[y0];
                __half2 lo = *reinterpret_cast<__half2*>(&cc.x);
                __half2 hi = *reinterpret_cast<__half2*>(&cc.y);
                __half2 r  = __hfma2(__hsub2(hi, lo), __float2half2_rn(wy), lo);
                float2 rf = __half22float2(r);
                a0x += rf.x;
                a0y += rf.y;
            }
            {
                float2 cs = sh_cs[a + 1];
                float iy = fmaf(cs.y, Xp, fmaf(cs.x, Yp, 306.5f));
                int   y0 = (int)iy;
                float wy = iy - (float)y0;
                uint2 cc = colA[HPP + y0];
                __half2 lo = *reinterpret_cast<__half2*>(&cc.x);
                __half2 hi = *reinterpret_cast<__half2*>(&cc.y);
                __half2 r  = __hfma2(__hsub2(hi, lo), __float2half2_rn(wy), lo);
                float2 rf = __half22float2(r);
                a1x += rf.x;
                a1y += rf.y;
            }
        }
    } else {
        // General path. Zero-padded table removes all y masking/clamping;
        // x masking collapses to wxe = clamp(min(ix+1, 614-ix), 0, 1):
        //   ix in [-1,0):  vx0=0, vx1=1 -> wxe = wx   = ix+1
        //   ix in [0,613): vx0=vx1=1    -> wxe = 1
        //   ix in [613,614): vx0=1,vx1=0-> wxe = 1-wx = 614-ix
        //   else 0.
        const uint2* __restrict__ colA = g_colh + PADR;
        #pragma unroll 2
        for (int a = 0; a < A_N; ++a, colA += HPP) {
            float2 cs = sh_cs[a];
            float c = cs.x, s = cs.y;
            float ix = fmaf(c, Xp, fmaf(-s, Yp, 306.5f));
            float iy = fmaf(s, Xp, fmaf(c, Yp, 306.5f));
            float wxe = fmaxf(fminf(fminf(ix + 1.0f, 614.0f - ix), 1.0f), 0.0f);
            float y0f = floorf(iy);
            int   y0  = (int)y0f;               // in [-56, 667] -> padded range
            float wy  = iy - y0f;
            uint2 cc = colA[y0];
            __half2 lo = *reinterpret_cast<__half2*>(&cc.x);
            __half2 hi = *reinterpret_cast<__half2*>(&cc.y);
            __half2 r  = __hfma2(__hsub2(hi, lo), __float2half2_rn(wy), lo);
            float2 rf = __half22float2(r);
            a0x = fmaf(wxe, rf.x, a0x);
            a0y = fmaf(wxe, rf.y, a0y);
        }
    }

    const float scale = (float)(1.0 / (180.0 + 1e-6));
    int o = y * HOUT + x;
    out[o]               = (a0x + a1x) * scale;
    out[o + HOUT * HOUT] = (a0y + a1y) * scale;   // batch 1 (out shape (2,1,512,512))
}

extern "C" void kernel_launch(void* const* d_in, const int* in_sizes, int n_in,
                              void* d_out, int out_size) {
    const float* sino   = (const float*)d_in[0];
    const float* angles = (const float*)d_in[1];
    float* out = (float*)d_out;

    col_kernel<<<(A_N * HPP + 255) / 256, 256>>>(sino);

    dim3 blk(32, 8);
    dim3 grd(HOUT / 32, HOUT / 8);   // 16 x 64 = 1024 CTAs, single resident wave
    bp_kernel<<<grd, blk>>>(angles, out);
}